// round 10
// baseline (speedup 1.0000x reference)
#include <cuda_runtime.h>
#include <cstdint>

// out[m][d] = sum_k x[m][k] * W[k][d];  M=8192, K=4096, N=32, fp32.
//
// bf16x3 split GEMM on mma.sync (tcgen05 rejected by harness sm_103 target).
//   D += Ahi*Bhi + Ahi*Blo + Alo*Bhi  (fp32 accum), rel_err ~5e-6.
//
// R9: clean occupancy experiment. R6/R7 "more warps" attempts were confounded
// by reg caps (spills). Here the per-warp working set is halved instead:
//  - warp tile 16x32 (8 warps/CTA): 16 accumulators, 16 A regs.
//  - B = per-CTA smem fragment table (32KB static), read in-step via
//    conflict-free swizzled LDS.128 (no B register double-buffer).
//  - NO launch_bounds cap; expect ~80 regs -> ~24 warps/SM (was 13.8).
//  - KSPLIT=16, 1024 CTAs, single kernel, fused deterministic reduction.

#define M_TOTAL 8192
#define K_TOTAL 4096
#define N_OUT   32
#define KSPLIT  16
#define KPER    (K_TOTAL / KSPLIT)     // 256
#define NIT     (KPER / 16)            // 16 k-steps per CTA
#define WARPS_CTA 8
#define THREADS  (WARPS_CTA * 32)      // 256
#define MB_ROWS  128
#define NMB      (M_TOTAL / MB_ROWS)   // 64
#define NCTA     (NMB * KSPLIT)        // 1024
#define NBENT    (NIT * 4 * 2 * 8)     // 1024 entries (uint4) per table

__device__ float g_part[(size_t)KSPLIT * M_TOTAL * N_OUT];  // 16 MB (L2)
__device__ int   g_cnt[NMB];

__device__ __forceinline__ void split2(float f0, float f1,
                                       uint32_t& hp, uint32_t& lp) {
    asm("cvt.rn.bf16x2.f32 %0, %1, %2;" : "=r"(hp) : "f"(f1), "f"(f0));
    float h0 = __uint_as_float(hp << 16);
    float h1 = __uint_as_float(hp & 0xffff0000u);
    float g0 = f0 - h0, g1 = f1 - h1;
    asm("cvt.rn.bf16x2.f32 %0, %1, %2;" : "=r"(lp) : "f"(g1), "f"(g0));
}

__device__ __forceinline__ void mma16816(float* d, const uint32_t* a,
                                         uint32_t b0, uint32_t b1) {
    asm volatile(
        "mma.sync.aligned.m16n8k16.row.col.f32.bf16.bf16.f32 "
        "{%0,%1,%2,%3}, {%4,%5,%6,%7}, {%8,%9}, {%0,%1,%2,%3};"
        : "+f"(d[0]), "+f"(d[1]), "+f"(d[2]), "+f"(d[3])
        : "r"(a[0]), "r"(a[1]), "r"(a[2]), "r"(a[3]), "r"(b0), "r"(b1));
}

// table slot for (st, c, h, r): swizzle r' = (r + 2c) & 7 makes the 8-lane
// LDS.128 phases (r x c) hit 8 distinct 16B offsets mod 128B.
__device__ __forceinline__ int uidx(int st, int c, int h, int r) {
    return ((st * 4 + c) * 2 + h) * 8 + ((r + 2 * c) & 7);
}

__global__ void __launch_bounds__(THREADS)
gemm_hmma_kernel(const float* __restrict__ x, const float* __restrict__ w,
                 float* __restrict__ out) {
    __shared__ __align__(16) uint4 sBhi[NBENT];   // 16 KB
    __shared__ __align__(16) uint4 sBlo[NBENT];   // 16 KB

    const int tid  = threadIdx.x;
    const int wid  = tid >> 5, lane = tid & 31;
    const int mb   = blockIdx.x & (NMB - 1);
    const int kp   = blockIdx.x >> 6;
    const int k0   = kp * KPER;
    const int m0   = mb * MB_ROWS + wid * 16;
    const int r    = lane >> 2;
    const int c    = lane & 3;

    // ---- build B fragment table (4 entries / thread, W is L2-hot) ----
    #pragma unroll
    for (int q = 0; q < NBENT / THREADS; q++) {
        const int e  = q * THREADS + tid;
        const int er = e & 7, eh = (e >> 3) & 1, ec = (e >> 4) & 3, es = e >> 6;
        const int k  = k0 + es * 16 + ec * 4 + eh * 2;
        uint32_t hi[4], lo[4];
        #pragma unroll
        for (int j = 0; j < 4; j++) {
            const int n = j * 8 + er;
            split2(w[(size_t)k * N_OUT + n], w[(size_t)(k + 1) * N_OUT + n],
                   hi[j], lo[j]);
        }
        const int u = uidx(es, ec, eh, er);
        sBhi[u] = make_uint4(hi[0], hi[1], hi[2], hi[3]);
        sBlo[u] = make_uint4(lo[0], lo[1], lo[2], lo[3]);
    }
    __syncthreads();

    const float* xa = x + (size_t)m0 * K_TOTAL + k0;

    struct AF { float4 p0, p1; };        // rows r, r+8
    auto load_a = [&](int it, AF& a) {
        const int col = it * 16 + c * 4;
        a.p0 = *(const float4*)(xa + (size_t)r       * K_TOTAL + col);
        a.p1 = *(const float4*)(xa + (size_t)(r + 8) * K_TOTAL + col);
    };

    float d[4][4];
    #pragma unroll
    for (int j = 0; j < 4; j++)
        #pragma unroll
        for (int q = 0; q < 4; q++) d[j][q] = 0.f;

    const int ubase = uidx(0, c, 0, r);   // step stride +64, h stride +8

    auto step = [&](const AF& a, int it) {
        // B: 4 conflict-free LDS.128 (no double-buffer; 29cyc LDS)
        const int u = ubase + it * 64;
        const uint4 h0 = sBhi[u], h1 = sBhi[u + 8];
        const uint4 l0 = sBlo[u], l1 = sBlo[u + 8];
        // A: split fp32 -> hi/lo bf16x2 fragments
        uint32_t ahi[4], alo[4];
        split2(a.p0.x, a.p0.y, ahi[0], alo[0]);
        split2(a.p1.x, a.p1.y, ahi[1], alo[1]);
        split2(a.p0.z, a.p0.w, ahi[2], alo[2]);
        split2(a.p1.z, a.p1.w, ahi[3], alo[3]);
        const uint32_t* bh0 = &h0.x; const uint32_t* bh1 = &h1.x;
        const uint32_t* bl0 = &l0.x; const uint32_t* bl1 = &l1.x;
        #pragma unroll
        for (int j = 0; j < 4; j++) {
            mma16816(d[j], ahi, bh0[j], bh1[j]);
            mma16816(d[j], ahi, bl0[j], bl1[j]);
            mma16816(d[j], alo, bh0[j], bh1[j]);
        }
    };

    AF a0, a1;
    load_a(0, a0);
    #pragma unroll 1
    for (int it = 0; it < NIT; it += 2) {
        const int n1 = (it + 1 < NIT) ? it + 1 : it;
        load_a(n1, a1);
        step(a0, it);
        const int n2 = (it + 2 < NIT) ? it + 2 : it;
        load_a(n2, a0);
        step(a1, n1);
    }

    // ---- store partials: rows r / r+8, cols j*8 + 2c ----
    float* base = g_part + ((size_t)kp * M_TOTAL + m0) * N_OUT;
    #pragma unroll
    for (int j = 0; j < 4; j++) {
        const int col = j * 8 + c * 2;
        *(float2*)(base + (size_t)r       * N_OUT + col) =
            make_float2(d[j][0], d[j][1]);
        *(float2*)(base + (size_t)(r + 8) * N_OUT + col) =
            make_float2(d[j][2], d[j][3]);
    }

    // ---- deterministic fused reduction (last CTA per m-block) ----
    __shared__ int s_last;
    __threadfence();
    __syncthreads();
    if (tid == 0) {
        s_last = (atomicAdd(&g_cnt[mb], 1) == KSPLIT - 1);
        if (s_last) __threadfence();
    }
    __syncthreads();
    if (s_last) {
        const int nf4 = MB_ROWS * N_OUT / 4;              // 1024 float4
        const float4* sc = (const float4*)g_part;
        float4* dst = (float4*)out + (size_t)mb * nf4;
        #pragma unroll 1
        for (int q = tid; q < nf4; q += THREADS) {
            const size_t o = (size_t)mb * nf4 + q;
            float4 sv = make_float4(0.f, 0.f, 0.f, 0.f);
            #pragma unroll 1
            for (int g = 0; g < 2; g++) {           // two batches of 8 (MLP 8)
                float4 v[8];
                #pragma unroll
                for (int p = 0; p < 8; p++)
                    v[p] = sc[(size_t)(g * 8 + p) * (M_TOTAL * N_OUT / 4) + o];
                #pragma unroll
                for (int p = 0; p < 8; p++) {       // fixed order: deterministic
                    sv.x += v[p].x; sv.y += v[p].y;
                    sv.z += v[p].z; sv.w += v[p].w;
                }
            }
            dst[q] = sv;
        }
        if (tid == 0) g_cnt[mb] = 0;   // reset for graph replay
    }
}

extern "C" void kernel_launch(void* const* d_in, const int* in_sizes, int n_in,
                              void* d_out, int out_size) {
    const float* x = (const float*)d_in[0];   // [8192, 4096]
    const float* w = (const float*)d_in[1];   // [4096, 32]
    float* out = (float*)d_out;               // [8192, 32]

    gemm_hmma_kernel<<<NCTA, THREADS>>>(x, w, out);
}

// round 11
// speedup vs baseline: 1.2555x; 1.2555x over previous
#include <cuda_runtime.h>
#include <cstdint>

// out[m][d] = sum_k x[m][k] * W[k][d];  M=8192, K=4096, N=32, fp32.
//
// bf16x3 split GEMM on mma.sync (tcgen05 rejected by harness sm_103 target).
//   D += Ahi*Bhi + Ahi*Blo + Alo*Bhi  (fp32 accum), rel_err ~5e-6.
//
// R10 = R9 without the tail. R9 proved 64-reg 8-warp CTAs hit 4 CTAs/SM, but
// grid=1024 meant 1.73 waves (wave 2 = straggler tail). Here:
//  - KSPLIT=8 -> 512 CTAs x 256 thr = ONE wave at 32 warps/SM for the whole
//    kernel (launch_bounds(256,4) pins 64 regs, R9's natural allocation).
//  - NIT=32 steps; 32KB B-fragment table rebuilt once mid-loop (2 halves).
//  - partial scratch halves to 8 MB; fused deterministic 8-way reduction.

#define M_TOTAL 8192
#define K_TOTAL 4096
#define N_OUT   32
#define KSPLIT  8
#define KPER    (K_TOTAL / KSPLIT)     // 512
#define KHALFC  256                    // k per table build
#define NITH    (KHALFC / 16)          // 16 steps per half
#define WARPS_CTA 8
#define THREADS  (WARPS_CTA * 32)      // 256
#define MB_ROWS  128
#define NMB      (M_TOTAL / MB_ROWS)   // 64
#define NCTA     (NMB * KSPLIT)        // 512
#define NBENT    (NITH * 4 * 2 * 8)    // 1024 entries (uint4) per table

__device__ float g_part[(size_t)KSPLIT * M_TOTAL * N_OUT];  // 8 MB (L2)
__device__ int   g_cnt[NMB];

__device__ __forceinline__ void split2(float f0, float f1,
                                       uint32_t& hp, uint32_t& lp) {
    asm("cvt.rn.bf16x2.f32 %0, %1, %2;" : "=r"(hp) : "f"(f1), "f"(f0));
    float h0 = __uint_as_float(hp << 16);
    float h1 = __uint_as_float(hp & 0xffff0000u);
    float g0 = f0 - h0, g1 = f1 - h1;
    asm("cvt.rn.bf16x2.f32 %0, %1, %2;" : "=r"(lp) : "f"(g1), "f"(g0));
}

__device__ __forceinline__ void mma16816(float* d, const uint32_t* a,
                                         uint32_t b0, uint32_t b1) {
    asm volatile(
        "mma.sync.aligned.m16n8k16.row.col.f32.bf16.bf16.f32 "
        "{%0,%1,%2,%3}, {%4,%5,%6,%7}, {%8,%9}, {%0,%1,%2,%3};"
        : "+f"(d[0]), "+f"(d[1]), "+f"(d[2]), "+f"(d[3])
        : "r"(a[0]), "r"(a[1]), "r"(a[2]), "r"(a[3]), "r"(b0), "r"(b1));
}

// table slot for (st, c, h, r): swizzle r' = (r + 2c) & 7 keeps each 8-lane
// LDS.128 phase on 8 distinct 16B offsets mod 128B (conflict-free).
__device__ __forceinline__ int uidx(int st, int c, int h, int r) {
    return ((st * 4 + c) * 2 + h) * 8 + ((r + 2 * c) & 7);
}

__global__ void __launch_bounds__(THREADS, 4)
gemm_hmma_kernel(const float* __restrict__ x, const float* __restrict__ w,
                 float* __restrict__ out) {
    __shared__ __align__(16) uint4 sBhi[NBENT];   // 16 KB
    __shared__ __align__(16) uint4 sBlo[NBENT];   // 16 KB

    const int tid  = threadIdx.x;
    const int wid  = tid >> 5, lane = tid & 31;
    const int mb   = blockIdx.x & (NMB - 1);
    const int kp   = blockIdx.x >> 6;
    const int k0   = kp * KPER;
    const int m0   = mb * MB_ROWS + wid * 16;
    const int r    = lane >> 2;
    const int c    = lane & 3;

    float d[4][4];
    #pragma unroll
    for (int j = 0; j < 4; j++)
        #pragma unroll
        for (int q = 0; q < 4; q++) d[j][q] = 0.f;

    const int ubase = uidx(0, c, 0, r);   // step stride +64 words, h stride +8

    #pragma unroll 1
    for (int half = 0; half < 2; half++) {
        const int kh = k0 + half * KHALFC;

        // ---- (re)build B fragment table for this half (W is L2-hot) ----
        if (half) __syncthreads();        // everyone done reading old table
        #pragma unroll
        for (int q = 0; q < NBENT / THREADS; q++) {
            const int e  = q * THREADS + tid;
            const int er = e & 7, eh = (e >> 3) & 1;
            const int ec = (e >> 4) & 3, es = e >> 6;
            const int k  = kh + es * 16 + ec * 4 + eh * 2;
            uint32_t hi[4], lo[4];
            #pragma unroll
            for (int j = 0; j < 4; j++) {
                const int n = j * 8 + er;
                split2(w[(size_t)k * N_OUT + n],
                       w[(size_t)(k + 1) * N_OUT + n], hi[j], lo[j]);
            }
            const int u = uidx(es, ec, eh, er);
            sBhi[u] = make_uint4(hi[0], hi[1], hi[2], hi[3]);
            sBlo[u] = make_uint4(lo[0], lo[1], lo[2], lo[3]);
        }
        __syncthreads();

        const float* xa = x + (size_t)m0 * K_TOTAL + kh;

        struct AF { float4 p0, p1; };     // rows r, r+8
        auto load_a = [&](int it, AF& a) {
            const int col = it * 16 + c * 4;
            a.p0 = *(const float4*)(xa + (size_t)r       * K_TOTAL + col);
            a.p1 = *(const float4*)(xa + (size_t)(r + 8) * K_TOTAL + col);
        };
        auto step = [&](const AF& a, int it) {
            const int u = ubase + it * 64;
            const uint4 h0 = sBhi[u], h1 = sBhi[u + 8];
            const uint4 l0 = sBlo[u], l1 = sBlo[u + 8];
            uint32_t ahi[4], alo[4];
            split2(a.p0.x, a.p0.y, ahi[0], alo[0]);
            split2(a.p1.x, a.p1.y, ahi[1], alo[1]);
            split2(a.p0.z, a.p0.w, ahi[2], alo[2]);
            split2(a.p1.z, a.p1.w, ahi[3], alo[3]);
            const uint32_t* bh0 = &h0.x; const uint32_t* bh1 = &h1.x;
            const uint32_t* bl0 = &l0.x; const uint32_t* bl1 = &l1.x;
            #pragma unroll
            for (int j = 0; j < 4; j++) {
                mma16816(d[j], ahi, bh0[j], bh1[j]);
                mma16816(d[j], ahi, bl0[j], bl1[j]);
                mma16816(d[j], alo, bh0[j], bh1[j]);
            }
        };

        AF a0, a1;
        load_a(0, a0);
        #pragma unroll 1
        for (int it = 0; it < NITH; it += 2) {
            const int n1 = (it + 1 < NITH) ? it + 1 : it;
            load_a(n1, a1);
            step(a0, it);
            const int n2 = (it + 2 < NITH) ? it + 2 : it;
            load_a(n2, a0);
            step(a1, n1);
        }
    }

    // ---- store partials: rows r / r+8, cols j*8 + 2c ----
    float* base = g_part + ((size_t)kp * M_TOTAL + m0) * N_OUT;
    #pragma unroll
    for (int j = 0; j < 4; j++) {
        const int col = j * 8 + c * 2;
        *(float2*)(base + (size_t)r       * N_OUT + col) =
            make_float2(d[j][0], d[j][1]);
        *(float2*)(base + (size_t)(r + 8) * N_OUT + col) =
            make_float2(d[j][2], d[j][3]);
    }

    // ---- deterministic fused reduction (last CTA per m-block) ----
    __shared__ int s_last;
    __threadfence();
    __syncthreads();
    if (tid == 0) {
        s_last = (atomicAdd(&g_cnt[mb], 1) == KSPLIT - 1);
        if (s_last) __threadfence();
    }
    __syncthreads();
    if (s_last) {
        const int nf4 = MB_ROWS * N_OUT / 4;              // 1024 float4
        const float4* sc = (const float4*)g_part;
        float4* dst = (float4*)out + (size_t)mb * nf4;
        #pragma unroll 1
        for (int q = tid; q < nf4; q += THREADS) {
            const size_t o = (size_t)mb * nf4 + q;
            float4 v[KSPLIT];
            #pragma unroll
            for (int p = 0; p < KSPLIT; p++)            // MLP 8
                v[p] = sc[(size_t)p * (M_TOTAL * N_OUT / 4) + o];
            float4 sv = v[0];
            #pragma unroll
            for (int p = 1; p < KSPLIT; p++) {          // fixed order
                sv.x += v[p].x; sv.y += v[p].y;
                sv.z += v[p].z; sv.w += v[p].w;
            }
            dst[q] = sv;
        }
        if (tid == 0) g_cnt[mb] = 0;   // reset for graph replay
    }
}

extern "C" void kernel_launch(void* const* d_in, const int* in_sizes, int n_in,
                              void* d_out, int out_size) {
    const float* x = (const float*)d_in[0];   // [8192, 4096]
    const float* w = (const float*)d_in[1];   // [4096, 32]
    float* out = (float*)d_out;               // [8192, 32]

    gemm_hmma_kernel<<<NCTA, THREADS>>>(x, w, out);
}